// round 2
// baseline (speedup 1.0000x reference)
#include <cuda_runtime.h>
#include <math.h>

#define L 2048
#define TOKS 512
#define CA 128
#define CP 16
#define CT 384
#define NH 4
#define HD 32
#define FFDIM 512
#define NBLK 3
#define F1D 388
#define KSPLIT 4

#define OFF_A 0
#define OFF_Q (TOKS*CT)
#define OFF_CL (OFF_Q + L*CA)
#define OFF_P (OFF_CL + L*CA)

// ---------------- scratch (static device arrays; no runtime allocation) ----------------
__device__ float g_Q  [L*CA];
__device__ float g_x  [L*CA];
__device__ float g_qm [L*CA];
__device__ float g_km [L*CA];
__device__ float g_vm [L*CA];
__device__ float g_o  [L*CA];
__device__ float g_ff [L*FFDIM];
__device__ float g_sl [L*CP];
__device__ float g_sm [L*CP];
__device__ float g_bias[(size_t)NBLK*NH*L*L];           // 192 MB, layout [b][h][l][m]
__device__ float g_pmax[KSPLIT*L*NH];
__device__ float g_psum[KSPLIT*L*NH];
__device__ float g_pacc[(size_t)KSPLIT*L*NH*HD];

// ---------------- C_L = concat(feat) @ W_in ; also seeds residual stream Q ----------------
__global__ void k_cl(const float* __restrict__ pos, const float* __restrict__ charge,
                     const float* __restrict__ elem, const float* __restrict__ chars,
                     const float* __restrict__ Win, float* __restrict__ outCL)
{
    __shared__ float f[F1D];
    int l = blockIdx.x, t = threadIdx.x;
    if (t < 3)  f[t]   = pos[l*3 + t];
    if (t == 3) f[3]   = charge[l];
    f[4   + t] = elem [l*128 + t];
    f[132 + t] = chars[l*256 + t];
    f[260 + t] = chars[l*256 + 128 + t];
    __syncthreads();
    float acc = 0.f;
    #pragma unroll 4
    for (int k = 0; k < F1D; k++) acc += f[k] * Win[(size_t)k*CA + t];
    outCL[(size_t)l*CA + t] = acc;
    g_Q  [(size_t)l*CA + t] = acc;
}

// ---------------- sl = relu(C_L)@W_sl, sm = relu(C_L)@W_sm ----------------
__global__ void k_slsm(const float* __restrict__ CL, const float* __restrict__ Wsl,
                       const float* __restrict__ Wsm)
{
    __shared__ float r[128];
    int l = blockIdx.x, t = threadIdx.x;
    r[t] = fmaxf(CL[(size_t)l*128 + t], 0.f);
    __syncthreads();
    if (t < 16) {
        float a = 0.f;
        for (int k = 0; k < 128; k++) a += r[k] * Wsl[k*16 + t];
        g_sl[l*16 + t] = a;
    } else if (t < 32) {
        int c = t - 16;
        float a = 0.f;
        for (int k = 0; k < 128; k++) a += r[k] * Wsm[k*16 + c];
        g_sm[l*16 + c] = a;
    }
}

// ---------------- pair features + pair MLP + fused bias (all 3 blocks) ----------------
__global__ void __launch_bounds__(128)
k_pair(const float* __restrict__ pos, const int* __restrict__ uid,
       const float* __restrict__ Wd,  const float* __restrict__ Wiv,
       const float* __restrict__ Wvm, const float* __restrict__ Wp1,
       const float* __restrict__ Wp2, const float* __restrict__ Wp3,
       const float* __restrict__ Wb,  float* __restrict__ outP)
{
    __shared__ float wd[48], wiv[16], wvm[16], w1[256], w2[256], w3[256], wb[192], sl[16], pl[3];
    __shared__ int ul;
    int l = blockIdx.y;
    int t = threadIdx.x;
    int m = blockIdx.x*128 + t;
    if (t < 48) wd[t] = Wd[t];
    if (t < 16) { wiv[t] = Wiv[t]; wvm[t] = Wvm[t]; sl[t] = g_sl[l*16 + t]; }
    if (t < 3)  pl[t] = pos[l*3 + t];
    if (t == 0) ul = uid[l];
    w1[t] = Wp1[t]; w1[t+128] = Wp1[t+128];
    w2[t] = Wp2[t]; w2[t+128] = Wp2[t+128];
    w3[t] = Wp3[t]; w3[t+128] = Wp3[t+128];
    if (t < 64) { wb[t] = Wb[t]; wb[t+64] = Wb[t+64]; wb[t+128] = Wb[t+128]; }
    __syncthreads();

    float d0 = pl[0] - pos[m*3+0];
    float d1 = pl[1] - pos[m*3+1];
    float d2 = pl[2] - pos[m*3+2];
    float iv = 1.f / (1.f + sqrtf(d0*d0 + d1*d1 + d2*d2));
    float vf = (ul == uid[m]) ? 1.f : 0.f;

    float smv[16];
    const float4* sm4 = (const float4*)(g_sm + m*16);
    #pragma unroll
    for (int i = 0; i < 4; i++) {
        float4 v = sm4[i];
        smv[4*i] = v.x; smv[4*i+1] = v.y; smv[4*i+2] = v.z; smv[4*i+3] = v.w;
    }

    float p[16];
    #pragma unroll
    for (int c = 0; c < 16; c++)
        p[c] = vf*(d0*wd[c] + d1*wd[16+c] + d2*wd[32+c] + iv*wiv[c] + wvm[c]) + sl[c] + smv[c];

    float pr[16];
    #pragma unroll
    for (int c = 0; c < 16; c++) pr[c] = fmaxf(p[c], 0.f);

    float a[16];
    #pragma unroll
    for (int c = 0; c < 16; c++) {
        float s = 0.f;
        #pragma unroll
        for (int j = 0; j < 16; j++) s += pr[j] * w1[j*16 + c];
        a[c] = fmaxf(s, 0.f);
    }
    float bb[16];
    #pragma unroll
    for (int c = 0; c < 16; c++) {
        float s = 0.f;
        #pragma unroll
        for (int j = 0; j < 16; j++) s += a[j] * w2[j*16 + c];
        bb[c] = fmaxf(s, 0.f);
    }
    #pragma unroll
    for (int c = 0; c < 16; c++) {
        float s = 0.f;
        #pragma unroll
        for (int j = 0; j < 16; j++) s += bb[j] * w3[j*16 + c];
        p[c] += s;
    }

    // store P to output
    float4* dst = (float4*)(outP + ((size_t)l*L + m)*16);
    dst[0] = make_float4(p[0],  p[1],  p[2],  p[3]);
    dst[1] = make_float4(p[4],  p[5],  p[6],  p[7]);
    dst[2] = make_float4(p[8],  p[9],  p[10], p[11]);
    dst[3] = make_float4(p[12], p[13], p[14], p[15]);

    // fused bias for all 3 transformer blocks, layout [b][h][l][m]
    #pragma unroll
    for (int b = 0; b < NBLK; b++) {
        #pragma unroll
        for (int h = 0; h < NH; h++) {
            float s = 0.f;
            #pragma unroll
            for (int c = 0; c < 16; c++) s += p[c] * wb[b*64 + c*4 + h];
            g_bias[((size_t)(b*NH + h)*L + l)*L + m] = s;
        }
    }
}

// ---------------- layernorm (no affine), eps = 1e-5 ----------------
__global__ void k_ln(const float* __restrict__ in, float* __restrict__ out)
{
    __shared__ float sh[128];
    __shared__ float s_mu, s_rstd;
    int l = blockIdx.x, t = threadIdx.x;
    float v = in[(size_t)l*128 + t];
    sh[t] = v; __syncthreads();
    for (int s = 64; s > 0; s >>= 1) { if (t < s) sh[t] += sh[t+s]; __syncthreads(); }
    if (t == 0) s_mu = sh[0] * (1.f/128.f);
    __syncthreads();
    float d = v - s_mu;
    sh[t] = d*d; __syncthreads();
    for (int s = 64; s > 0; s >>= 1) { if (t < s) sh[t] += sh[t+s]; __syncthreads(); }
    if (t == 0) s_rstd = rsqrtf(sh[0] * (1.f/128.f) + 1e-5f);
    __syncthreads();
    out[(size_t)l*128 + t] = d * s_rstd;
}

// ---------------- generic row-GEMM: OUT[l, col] (+)= relu?(X[l,:] @ W) ----------------
__global__ void k_gemm(const float* __restrict__ X, const float* __restrict__ W,
                       float* __restrict__ OUT, int K, int N, int doRelu, int addTo)
{
    extern __shared__ float xs[];
    int l = blockIdx.x;
    int col = blockIdx.y*128 + threadIdx.x;
    for (int k = threadIdx.x; k < K; k += 128) xs[k] = X[(size_t)l*K + k];
    __syncthreads();
    float acc = 0.f;
    #pragma unroll 4
    for (int k = 0; k < K; k++) acc += xs[k] * W[(size_t)k*N + col];
    if (doRelu) acc = fmaxf(acc, 0.f);
    float* o = OUT + (size_t)l*N + col;
    if (addTo) *o += acc; else *o = acc;
}

// ---------------- attention: 128 queries x 1 head per block, key-split over z ----------------
__global__ void __launch_bounds__(128) k_attn_split(int b)
{
    int h  = blockIdx.y;
    int s  = blockIdx.z;
    int q0 = blockIdx.x * 128;
    int t  = threadIdx.x;
    int q  = q0 + t;

    __shared__ float ks[32*32];
    __shared__ float vs[32*32];
    __shared__ float bs[128*33];   // +1 pad: conflict-free bs[t*33+j]

    float qr[32];
    const float4* q4 = (const float4*)(g_qm + (size_t)q*CA + h*HD);
    #pragma unroll
    for (int i = 0; i < 8; i++) {
        float4 v = q4[i];
        qr[4*i] = v.x; qr[4*i+1] = v.y; qr[4*i+2] = v.z; qr[4*i+3] = v.w;
    }

    float mmax = -1e30f, ssum = 0.f, acc[32];
    #pragma unroll
    for (int d = 0; d < 32; d++) acc[d] = 0.f;
    const float scale = 0.1767766952966369f;   // 1/sqrt(32)

    const float* bsrc_base = g_bias + ((size_t)(b*NH + h)*L + q0)*L;
    int m_begin = s * (L/KSPLIT);
    int m_end   = m_begin + (L/KSPLIT);

    for (int m0 = m_begin; m0 < m_end; m0 += 32) {
        __syncthreads();
        for (int i = t; i < 256; i += 128) {           // 32 keys x 32 dims as float4
            int j = i >> 3, dq = i & 7;
            ((float4*)ks)[i] = ((const float4*)g_km)[(size_t)(m0+j)*32 + h*8 + dq];
            ((float4*)vs)[i] = ((const float4*)g_vm)[(size_t)(m0+j)*32 + h*8 + dq];
        }
        for (int i = t; i < 128*32; i += 128) {        // bias tile, coalesced over m
            int t2 = i >> 5, j = i & 31;
            bs[t2*33 + j] = bsrc_base[(size_t)t2*L + m0 + j];
        }
        __syncthreads();

        #pragma unroll 2
        for (int j = 0; j < 32; j++) {
            const float* kr = ks + j*32;
            float p0 = 0.f, p1 = 0.f, p2 = 0.f, p3 = 0.f;
            #pragma unroll
            for (int d = 0; d < 32; d += 4) {
                p0 += qr[d]   * kr[d];
                p1 += qr[d+1] * kr[d+1];
                p2 += qr[d+2] * kr[d+2];
                p3 += qr[d+3] * kr[d+3];
            }
            float logit = ((p0+p1) + (p2+p3)) * scale + bs[t*33 + j];
            if (logit > mmax) {
                float f = __expf(mmax - logit);
                ssum *= f;
                #pragma unroll
                for (int d = 0; d < 32; d++) acc[d] *= f;
                mmax = logit;
            }
            float e = __expf(logit - mmax);
            ssum += e;
            const float* vr = vs + j*32;
            #pragma unroll
            for (int d = 0; d < 32; d++) acc[d] += e * vr[d];
        }
    }

    int pidx = (s*L + q)*NH + h;
    g_pmax[pidx] = mmax;
    g_psum[pidx] = ssum;
    float* pa = g_pacc + (size_t)pidx*HD;
    #pragma unroll
    for (int d = 0; d < 32; d++) pa[d] = acc[d];
}

__global__ void k_attn_comb()
{
    int q = blockIdx.x;
    int t = threadIdx.x;            // 128 threads = 4 heads x 32 dims
    int h = t >> 5, d = t & 31;
    float pm[KSPLIT], gm = -1e30f;
    #pragma unroll
    for (int s = 0; s < KSPLIT; s++) {
        pm[s] = g_pmax[(s*L + q)*NH + h];
        gm = fmaxf(gm, pm[s]);
    }
    float denom = 0.f, o = 0.f;
    #pragma unroll
    for (int s = 0; s < KSPLIT; s++) {
        float f = __expf(pm[s] - gm);
        int pidx = (s*L + q)*NH + h;
        denom += g_psum[pidx] * f;
        o     += g_pacc[(size_t)pidx*HD + d] * f;
    }
    g_o[(size_t)q*CA + h*HD + d] = o / denom;
}

// ---------------- final Q copy to output ----------------
__global__ void k_copyQ(float* __restrict__ dst)
{
    int i = blockIdx.x*256 + threadIdx.x;
    dst[i] = g_Q[i];
}

// ---------------- segment mean (deterministic, sorted token map) ----------------
__global__ void k_seg(const float* __restrict__ pQ, const int* __restrict__ tok,
                      float* __restrict__ outA)
{
    __shared__ int slo, shi;
    int i = blockIdx.x;
    if (threadIdx.x == 0) {
        int lo = 0, hi = L;
        while (lo < hi) { int mid = (lo+hi) >> 1; if (tok[mid] < i) lo = mid+1; else hi = mid; }
        slo = lo;
        int lo2 = lo, hi2 = L;
        while (lo2 < hi2) { int mid = (lo2+hi2) >> 1; if (tok[mid] < i+1) lo2 = mid+1; else hi2 = mid; }
        shi = lo2;
    }
    __syncthreads();
    int lo = slo, hi = shi;
    float inv = (hi > lo) ? 1.f/(float)(hi - lo) : 0.f;
    int c = threadIdx.x;   // 384 threads
    float a = 0.f;
    for (int at = lo; at < hi; at++) a += pQ[(size_t)at*CT + c];
    outA[(size_t)i*CT + c] = a * inv;
}

// ---------------- launch ----------------
extern "C" void kernel_launch(void* const* d_in, const int* in_sizes, int n_in,
                              void* d_out, int out_size)
{
    const float* pos    = (const float*)d_in[0];
    const float* charge = (const float*)d_in[1];
    const float* elem   = (const float*)d_in[2];
    const float* chars  = (const float*)d_in[3];
    const int*   uid    = (const int*)  d_in[4];
    const int*   tok    = (const int*)  d_in[5];
    const float* Win    = (const float*)d_in[6];
    const float* Wd     = (const float*)d_in[7];
    const float* Wiv    = (const float*)d_in[8];
    const float* Wvmw   = (const float*)d_in[9];
    const float* Wsl    = (const float*)d_in[10];
    const float* Wsm    = (const float*)d_in[11];
    const float* Wp1    = (const float*)d_in[12];
    const float* Wp2    = (const float*)d_in[13];
    const float* Wp3    = (const float*)d_in[14];
    const float* Wqtok  = (const float*)d_in[15];
    const float* Wq     = (const float*)d_in[16];
    const float* Wk     = (const float*)d_in[17];
    const float* Wv     = (const float*)d_in[18];
    const float* Wb     = (const float*)d_in[19];
    const float* Wo     = (const float*)d_in[20];
    const float* Wt1    = (const float*)d_in[21];
    const float* Wt2    = (const float*)d_in[22];

    float* out   = (float*)d_out;
    float* outA  = out + OFF_A;
    float* outQ  = out + OFF_Q;
    float* outCL = out + OFF_CL;
    float* outP  = out + OFF_P;

    float *pQbuf, *pX, *pQm, *pKm, *pVm, *pO, *pFF;
    cudaGetSymbolAddress((void**)&pQbuf, g_Q);
    cudaGetSymbolAddress((void**)&pX,    g_x);
    cudaGetSymbolAddress((void**)&pQm,   g_qm);
    cudaGetSymbolAddress((void**)&pKm,   g_km);
    cudaGetSymbolAddress((void**)&pVm,   g_vm);
    cudaGetSymbolAddress((void**)&pO,    g_o);
    cudaGetSymbolAddress((void**)&pFF,   g_ff);

    k_cl  <<<L, 128>>>(pos, charge, elem, chars, Win, outCL);
    k_slsm<<<L, 128>>>(outCL, Wsl, Wsm);
    k_pair<<<dim3(16, L), 128>>>(pos, uid, Wd, Wiv, Wvmw, Wp1, Wp2, Wp3, Wb, outP);

    for (int b = 0; b < NBLK; b++) {
        k_ln<<<L, 128>>>(pQbuf, pX);
        k_gemm<<<dim3(L,1), 128, CA*4>>>(pX, Wq + (size_t)b*CA*CA, pQm, CA, CA, 0, 0);
        k_gemm<<<dim3(L,1), 128, CA*4>>>(pX, Wk + (size_t)b*CA*CA, pKm, CA, CA, 0, 0);
        k_gemm<<<dim3(L,1), 128, CA*4>>>(pX, Wv + (size_t)b*CA*CA, pVm, CA, CA, 0, 0);
        k_attn_split<<<dim3(L/128, NH, KSPLIT), 128>>>(b);
        k_attn_comb <<<L, 128>>>();
        k_gemm<<<dim3(L,1), 128, CA*4>>>(pO, Wo + (size_t)b*CA*CA, pQbuf, CA, CA, 0, 1);
        k_ln<<<L, 128>>>(pQbuf, pX);
        k_gemm<<<dim3(L,4), 128, CA*4>>>(pX, Wt1 + (size_t)b*CA*FFDIM, pFF, CA, FFDIM, 1, 0);
        k_gemm<<<dim3(L,1), 128, FFDIM*4>>>(pFF, Wt2 + (size_t)b*FFDIM*CA, pQbuf, FFDIM, CA, 0, 1);
    }

    k_copyQ<<<(L*CA)/256, 256>>>(outQ);
    k_gemm<<<dim3(L,3), 128, CA*4>>>(pQbuf, Wqtok, pFF, CA, CT, 1, 0);
    k_seg<<<TOKS, CT>>>(pFF, tok, outA);
}

// round 4
// speedup vs baseline: 1.2167x; 1.2167x over previous
#include <cuda_runtime.h>
#include <math.h>

#define L 2048
#define TOKS 512
#define CA 128
#define CP 16
#define CT 384
#define NH 4
#define HD 32
#define FFDIM 512
#define NBLK 3
#define F1D 388
#define KSPLIT 8

#define OFF_A 0
#define OFF_Q (TOKS*CT)
#define OFF_CL (OFF_Q + L*CA)
#define OFF_P (OFF_CL + L*CA)

typedef unsigned long long u64;

// ---------------- f32x2 helpers ----------------
__device__ __forceinline__ u64 pack2(float lo, float hi) {
    u64 r; asm("mov.b64 %0, {%1, %2};" : "=l"(r) : "f"(lo), "f"(hi)); return r;
}
__device__ __forceinline__ void unpack2(u64 v, float& lo, float& hi) {
    asm("mov.b64 {%0, %1}, %2;" : "=f"(lo), "=f"(hi) : "l"(v));
}
__device__ __forceinline__ u64 fma2(u64 a, u64 b, u64 c) {
    u64 d; asm("fma.rn.f32x2 %0, %1, %2, %3;" : "=l"(d) : "l"(a), "l"(b), "l"(c)); return d;
}
__device__ __forceinline__ u64 mul2(u64 a, u64 b) {
    u64 d; asm("mul.rn.f32x2 %0, %1, %2;" : "=l"(d) : "l"(a), "l"(b)); return d;
}
__device__ __forceinline__ u64 add2(u64 a, u64 b) {
    u64 d; asm("add.rn.f32x2 %0, %1, %2;" : "=l"(d) : "l"(a), "l"(b)); return d;
}
__device__ __forceinline__ u64 relu2(u64 v) {
    float lo, hi; unpack2(v, lo, hi);
    return pack2(fmaxf(lo, 0.f), fmaxf(hi, 0.f));
}

// ---------------- scratch ----------------
__device__ float g_Q  [L*CA];
__device__ float g_qm [L*CA];
__device__ float g_km [L*CA];
__device__ float g_vm [L*CA];
__device__ float g_o  [L*CA];
__device__ float g_ff [L*FFDIM];
__device__ float g_sl [L*CP];
__device__ float g_sm [L*CP];
__device__ float g_bias[(size_t)NBLK*NH*L*L];           // [b][h][l][m]
__device__ float g_pmax[KSPLIT*L*NH];
__device__ float g_psum[KSPLIT*L*NH];
__device__ float g_pacc[(size_t)KSPLIT*L*NH*HD];

// ---------------- C_L = concat(feat) @ W_in ; seeds residual Q ----------------
__global__ void k_cl(const float* __restrict__ pos, const float* __restrict__ charge,
                     const float* __restrict__ elem, const float* __restrict__ chars,
                     const float* __restrict__ Win, float* __restrict__ outCL)
{
    __shared__ float f[F1D];
    int l = blockIdx.x, t = threadIdx.x;
    if (t < 3)  f[t]   = pos[l*3 + t];
    if (t == 3) f[3]   = charge[l];
    f[4   + t] = elem [l*128 + t];
    f[132 + t] = chars[l*256 + t];
    f[260 + t] = chars[l*256 + 128 + t];
    __syncthreads();
    float acc = 0.f;
    #pragma unroll 4
    for (int k = 0; k < F1D; k++) acc += f[k] * Win[(size_t)k*CA + t];
    outCL[(size_t)l*CA + t] = acc;
    g_Q  [(size_t)l*CA + t] = acc;
}

// ---------------- sl = relu(C_L)@W_sl, sm = relu(C_L)@W_sm ----------------
__global__ void k_slsm(const float* __restrict__ CL, const float* __restrict__ Wsl,
                       const float* __restrict__ Wsm)
{
    __shared__ float r[128];
    int l = blockIdx.x, t = threadIdx.x;
    r[t] = fmaxf(CL[(size_t)l*128 + t], 0.f);
    __syncthreads();
    if (t < 16) {
        float a = 0.f;
        for (int k = 0; k < 128; k++) a += r[k] * Wsl[k*16 + t];
        g_sl[l*16 + t] = a;
    } else if (t < 32) {
        int c = t - 16;
        float a = 0.f;
        for (int k = 0; k < 128; k++) a += r[k] * Wsm[k*16 + c];
        g_sm[l*16 + c] = a;
    }
}

// ---------------- pair features + pair MLP + fused bias, 2 atoms/thread via f32x2 ----------------
__global__ void __launch_bounds__(128)
k_pair(const float* __restrict__ pos, const int* __restrict__ uid,
       const float* __restrict__ Wd,  const float* __restrict__ Wiv,
       const float* __restrict__ Wvm, const float* __restrict__ Wp1,
       const float* __restrict__ Wp2, const float* __restrict__ Wp3,
       const float* __restrict__ Wb,  float* __restrict__ outP)
{
    __shared__ u64 wd2[48], wiv2[16], wvm2[16], w1_2[256], w2_2[256], w3_2[256], wb2[192], sl2[16];
    __shared__ float pl[3];
    __shared__ int ul;
    int l = blockIdx.y;
    int t = threadIdx.x;
    int m0 = blockIdx.x*256 + t;
    int m1 = m0 + 128;

    if (t < 48) wd2[t] = pack2(Wd[t], Wd[t]);
    if (t < 16) {
        wiv2[t] = pack2(Wiv[t], Wiv[t]);
        wvm2[t] = pack2(Wvm[t], Wvm[t]);
        float s = g_sl[l*16 + t];
        sl2[t]  = pack2(s, s);
    }
    if (t < 3)  pl[t] = pos[l*3 + t];
    if (t == 0) ul = uid[l];
    w1_2[t] = pack2(Wp1[t], Wp1[t]); w1_2[t+128] = pack2(Wp1[t+128], Wp1[t+128]);
    w2_2[t] = pack2(Wp2[t], Wp2[t]); w2_2[t+128] = pack2(Wp2[t+128], Wp2[t+128]);
    w3_2[t] = pack2(Wp3[t], Wp3[t]); w3_2[t+128] = pack2(Wp3[t+128], Wp3[t+128]);
    wb2[t] = pack2(Wb[t], Wb[t]);
    if (t < 64) wb2[t+128] = pack2(Wb[t+128], Wb[t+128]);
    __syncthreads();

    float a0 = pl[0] - pos[m0*3+0], b0 = pl[1] - pos[m0*3+1], c0 = pl[2] - pos[m0*3+2];
    float a1 = pl[0] - pos[m1*3+0], b1 = pl[1] - pos[m1*3+1], c1 = pl[2] - pos[m1*3+2];
    float iv0 = 1.f / (1.f + sqrtf(a0*a0 + b0*b0 + c0*c0));
    float iv1 = 1.f / (1.f + sqrtf(a1*a1 + b1*b1 + c1*c1));
    float vf0 = (ul == uid[m0]) ? 1.f : 0.f;
    float vf1 = (ul == uid[m1]) ? 1.f : 0.f;
    u64 d0_2 = pack2(a0, a1), d1_2 = pack2(b0, b1), d2_2 = pack2(c0, c1);
    u64 iv2  = pack2(iv0, iv1), vf2 = pack2(vf0, vf1);

    // sm rows for both atoms
    u64 sm2[16];
    {
        const float4* r0 = (const float4*)(g_sm + m0*16);
        const float4* r1 = (const float4*)(g_sm + m1*16);
        #pragma unroll
        for (int i = 0; i < 4; i++) {
            float4 v0 = r0[i], v1 = r1[i];
            sm2[4*i+0] = pack2(v0.x, v1.x);
            sm2[4*i+1] = pack2(v0.y, v1.y);
            sm2[4*i+2] = pack2(v0.z, v1.z);
            sm2[4*i+3] = pack2(v0.w, v1.w);
        }
    }

    u64 p2[16];
    #pragma unroll
    for (int c = 0; c < 16; c++) {
        u64 tmp = wvm2[c];
        tmp = fma2(iv2,  wiv2[c],    tmp);
        tmp = fma2(d2_2, wd2[32+c],  tmp);
        tmp = fma2(d1_2, wd2[16+c],  tmp);
        tmp = fma2(d0_2, wd2[c],     tmp);
        p2[c] = fma2(vf2, tmp, add2(sl2[c], sm2[c]));
    }

    u64 pr2[16];
    #pragma unroll
    for (int c = 0; c < 16; c++) pr2[c] = relu2(p2[c]);

    u64 aa2[16];
    #pragma unroll
    for (int c = 0; c < 16; c++) {
        u64 s = 0ull;
        #pragma unroll
        for (int j = 0; j < 16; j++) s = fma2(pr2[j], w1_2[j*16 + c], s);
        aa2[c] = relu2(s);
    }
    #pragma unroll
    for (int c = 0; c < 16; c++) {
        u64 s = 0ull;
        #pragma unroll
        for (int j = 0; j < 16; j++) s = fma2(aa2[j], w2_2[j*16 + c], s);
        pr2[c] = relu2(s);
    }
    #pragma unroll
    for (int c = 0; c < 16; c++) {
        u64 s = 0ull;
        #pragma unroll
        for (int j = 0; j < 16; j++) s = fma2(pr2[j], w3_2[j*16 + c], s);
        p2[c] = add2(p2[c], s);
    }

    // store P (both rows)
    float plo[16], phi[16];
    #pragma unroll
    for (int c = 0; c < 16; c++) unpack2(p2[c], plo[c], phi[c]);
    {
        float4* dst0 = (float4*)(outP + ((size_t)l*L + m0)*16);
        float4* dst1 = (float4*)(outP + ((size_t)l*L + m1)*16);
        #pragma unroll
        for (int i = 0; i < 4; i++) {
            dst0[i] = make_float4(plo[4*i], plo[4*i+1], plo[4*i+2], plo[4*i+3]);
            dst1[i] = make_float4(phi[4*i], phi[4*i+1], phi[4*i+2], phi[4*i+3]);
        }
    }

    // fused bias for all 3 blocks x 4 heads
    #pragma unroll
    for (int b = 0; b < NBLK; b++) {
        #pragma unroll
        for (int h = 0; h < NH; h++) {
            u64 s = 0ull;
            #pragma unroll
            for (int c = 0; c < 16; c++) s = fma2(p2[c], wb2[b*64 + c*4 + h], s);
            float lo, hi; unpack2(s, lo, hi);
            float* base = g_bias + ((size_t)(b*NH + h)*L + l)*L;
            base[m0] = lo;
            base[m1] = hi;
        }
    }
}

// ---------------- row-blocked GEMM with optional fused LN / relu / add, f32x2 ----------------
template<int K, int N, bool LNF, bool RELU, bool ADD>
__global__ void __launch_bounds__(128)
k_gemm2(const float* __restrict__ X, const float* __restrict__ W, float* __restrict__ OUT)
{
    constexpr int R  = 8;
    constexpr int NP = N/2;
    constexpr int GROUPS = (NP >= 128) ? 1 : (128 / NP);
    constexpr int RT = R / GROUPS;
    __shared__ u64 xs2[R*K];

    int r0 = blockIdx.x * R;
    int t  = threadIdx.x;

    if (LNF) {
        // K==128: 16 threads per row
        int r  = t >> 4, c0 = t & 15;
        const float* xr = X + (size_t)(r0 + r)*K;
        float v[8]; float s = 0.f, ss = 0.f;
        #pragma unroll
        for (int i = 0; i < 8; i++) { v[i] = xr[c0 + i*16]; s += v[i]; ss += v[i]*v[i]; }
        #pragma unroll
        for (int o = 8; o >= 1; o >>= 1) {
            s  += __shfl_xor_sync(0xffffffffu, s,  o);
            ss += __shfl_xor_sync(0xffffffffu, ss, o);
        }
        float mu   = s * (1.f/128.f);
        float rstd = rsqrtf(ss * (1.f/128.f) - mu*mu + 1e-5f);
        #pragma unroll
        for (int i = 0; i < 8; i++) {
            float nv = (v[i] - mu) * rstd;
            xs2[r*K + c0 + i*16] = pack2(nv, nv);
        }
    } else {
        const float* xb = X + (size_t)r0*K;
        for (int i = t; i < R*K; i += 128) { float v = xb[i]; xs2[i] = pack2(v, v); }
    }
    __syncthreads();

    const u64* W2 = (const u64*)W;   // [K][NP] packed col-pairs
    int cp0 = t % NP;
    int g   = t / NP;
    for (int cp = cp0; cp < NP; cp += 128) {
        u64 acc[RT];
        #pragma unroll
        for (int r = 0; r < RT; r++) acc[r] = 0ull;
        #pragma unroll 4
        for (int k = 0; k < K; k++) {
            u64 w2 = W2[(size_t)k*NP + cp];
            #pragma unroll
            for (int r = 0; r < RT; r++)
                acc[r] = fma2(xs2[(g*RT + r)*K + k], w2, acc[r]);
        }
        #pragma unroll
        for (int r = 0; r < RT; r++) {
            float lo, hi; unpack2(acc[r], lo, hi);
            if (RELU) { lo = fmaxf(lo, 0.f); hi = fmaxf(hi, 0.f); }
            float* o = OUT + (size_t)(r0 + g*RT + r)*N + 2*cp;
            if (ADD) { o[0] += lo; o[1] += hi; }
            else     { o[0]  = lo; o[1]  = hi; }
        }
    }
}

// ---------------- attention: 128 queries x 1 head, key-split; f32x2 + LDS.128 ----------------
__global__ void __launch_bounds__(128) k_attn_split(int b)
{
    int h  = blockIdx.y;
    int s  = blockIdx.z;
    int q0 = blockIdx.x * 128;
    int t  = threadIdx.x;
    int q  = q0 + t;

    __shared__ alignas(16) float ks[32*32];
    __shared__ alignas(16) float vs[32*32];
    __shared__ float bs[128*33];

    u64 qr2[16];
    {
        // 32 floats = 8 x ulonglong2 (16B each)
        const ulonglong2* q4 = (const ulonglong2*)(g_qm + (size_t)q*CA + h*HD);
        #pragma unroll
        for (int i = 0; i < 8; i++) {
            ulonglong2 v = q4[i];
            qr2[2*i]   = v.x;
            qr2[2*i+1] = v.y;
        }
    }

    float mmax = -1e30f, ssum = 0.f;
    u64 acc2[16];
    #pragma unroll
    for (int i = 0; i < 16; i++) acc2[i] = 0ull;
    const float scale = 0.1767766952966369f;

    const float* bsrc_base = g_bias + ((size_t)(b*NH + h)*L + q0)*L;
    int m_begin = s * (L/KSPLIT);
    int m_end   = m_begin + (L/KSPLIT);

    for (int m0 = m_begin; m0 < m_end; m0 += 32) {
        __syncthreads();
        for (int i = t; i < 256; i += 128) {
            int j = i >> 3, dq = i & 7;
            ((float4*)ks)[i] = ((const float4*)g_km)[(size_t)(m0+j)*32 + h*8 + dq];
            ((float4*)vs)[i] = ((const float4*)g_vm)[(size_t)(m0+j)*32 + h*8 + dq];
        }
        for (int i = t; i < 1024; i += 128) {
            int t2 = i >> 3, jv = i & 7;
            float4 v = *(const float4*)(bsrc_base + (size_t)t2*L + m0 + jv*4);
            float* d = bs + t2*33 + jv*4;
            d[0] = v.x; d[1] = v.y; d[2] = v.z; d[3] = v.w;
        }
        __syncthreads();

        #pragma unroll 2
        for (int j = 0; j < 32; j++) {
            const ulonglong2* k2 = (const ulonglong2*)(ks + j*32);
            u64 dp = 0ull;
            #pragma unroll
            for (int i = 0; i < 4; i++) {
                ulonglong2 kk = k2[i];
                dp = fma2(qr2[2*i],   kk.x, dp);
                dp = fma2(qr2[2*i+1], kk.y, dp);
            }
            const ulonglong2* k2b = k2 + 4;
            #pragma unroll
            for (int i = 0; i < 4; i++) {
                ulonglong2 kk = k2b[i];
                dp = fma2(qr2[8+2*i],   kk.x, dp);
                dp = fma2(qr2[8+2*i+1], kk.y, dp);
            }
            float dlo, dhi; unpack2(dp, dlo, dhi);
            float logit = (dlo + dhi) * scale + bs[t*33 + j];

            if (logit > mmax) {
                float f = __expf(mmax - logit);
                u64 f2 = pack2(f, f);
                ssum *= f;
                #pragma unroll
                for (int i = 0; i < 16; i++) acc2[i] = mul2(acc2[i], f2);
                mmax = logit;
            }
            float e = __expf(logit - mmax);
            ssum += e;
            u64 e2 = pack2(e, e);
            const ulonglong2* v2 = (const ulonglong2*)(vs + j*32);
            #pragma unroll
            for (int i = 0; i < 8; i++) {
                ulonglong2 vv = v2[i];
                acc2[2*i]   = fma2(e2, vv.x, acc2[2*i]);
                acc2[2*i+1] = fma2(e2, vv.y, acc2[2*i+1]);
            }
        }
    }

    int pidx = (s*L + q)*NH + h;
    g_pmax[pidx] = mmax;
    g_psum[pidx] = ssum;
    u64* pa = (u64*)(g_pacc + (size_t)pidx*HD);
    #pragma unroll
    for (int i = 0; i < 16; i++) pa[i] = acc2[i];
}

__global__ void k_attn_comb()
{
    int q = blockIdx.x;
    int t = threadIdx.x;            // 128 = 4 heads x 32 dims
    int h = t >> 5, d = t & 31;
    float pm[KSPLIT], gm = -1e30f;
    #pragma unroll
    for (int s = 0; s < KSPLIT; s++) {
        pm[s] = g_pmax[(s*L + q)*NH + h];
        gm = fmaxf(gm, pm[s]);
    }
    float denom = 0.f, o = 0.f;
    #pragma unroll
    for (int s = 0; s < KSPLIT; s++) {
        float f = __expf(pm[s] - gm);
        int pidx = (s*L + q)*NH + h;
        denom += g_psum[pidx] * f;
        o     += g_pacc[(size_t)pidx*HD + d] * f;
    }
    g_o[(size_t)q*CA + h*HD + d] = o / denom;
}

// ---------------- final Q copy ----------------
__global__ void k_copyQ(float* __restrict__ dst)
{
    int i = blockIdx.x*256 + threadIdx.x;
    dst[i] = g_Q[i];
}

// ---------------- segment mean ----------------
__global__ void k_seg(const float* __restrict__ pQ, const int* __restrict__ tok,
                      float* __restrict__ outA)
{
    __shared__ int slo, shi;
    int i = blockIdx.x;
    if (threadIdx.x == 0) {
        int lo = 0, hi = L;
        while (lo < hi) { int mid = (lo+hi) >> 1; if (tok[mid] < i) lo = mid+1; else hi = mid; }
        slo = lo;
        int lo2 = lo, hi2 = L;
        while (lo2 < hi2) { int mid = (lo2+hi2) >> 1; if (tok[mid] < i+1) lo2 = mid+1; else hi2 = mid; }
        shi = lo2;
    }
    __syncthreads();
    int lo = slo, hi = shi;
    float inv = (hi > lo) ? 1.f/(float)(hi - lo) : 0.f;
    int c = threadIdx.x;
    float a = 0.f;
    for (int at = lo; at < hi; at++) a += pQ[(size_t)at*CT + c];
    outA[(size_t)i*CT + c] = a * inv;
}

// ---------------- launch ----------------
extern "C" void kernel_launch(void* const* d_in, const int* in_sizes, int n_in,
                              void* d_out, int out_size)
{
    const float* pos    = (const float*)d_in[0];
    const float* charge = (const float*)d_in[1];
    const float* elem   = (const float*)d_in[2];
    const float* chars  = (const float*)d_in[3];
    const int*   uid    = (const int*)  d_in[4];
    const int*   tok    = (const int*)  d_in[5];
    const float* Win    = (const float*)d_in[6];
    const float* Wd     = (const float*)d_in[7];
    const float* Wiv    = (const float*)d_in[8];
    const float* Wvmw   = (const float*)d_in[9];
    const float* Wsl    = (const float*)d_in[10];
    const float* Wsm    = (const float*)d_in[11];
    const float* Wp1    = (const float*)d_in[12];
    const float* Wp2    = (const float*)d_in[13];
    const float* Wp3    = (const float*)d_in[14];
    const float* Wqtok  = (const float*)d_in[15];
    const float* Wq     = (const float*)d_in[16];
    const float* Wk     = (const float*)d_in[17];
    const float* Wv     = (const float*)d_in[18];
    const float* Wb     = (const float*)d_in[19];
    const float* Wo     = (const float*)d_in[20];
    const float* Wt1    = (const float*)d_in[21];
    const float* Wt2    = (const float*)d_in[22];

    float* out   = (float*)d_out;
    float* outA  = out + OFF_A;
    float* outQ  = out + OFF_Q;
    float* outCL = out + OFF_CL;
    float* outP  = out + OFF_P;

    float *pQbuf, *pQm, *pKm, *pVm, *pO, *pFF;
    cudaGetSymbolAddress((void**)&pQbuf, g_Q);
    cudaGetSymbolAddress((void**)&pQm,   g_qm);
    cudaGetSymbolAddress((void**)&pKm,   g_km);
    cudaGetSymbolAddress((void**)&pVm,   g_vm);
    cudaGetSymbolAddress((void**)&pO,    g_o);
    cudaGetSymbolAddress((void**)&pFF,   g_ff);

    k_cl  <<<L, 128>>>(pos, charge, elem, chars, Win, outCL);
    k_slsm<<<L, 128>>>(outCL, Wsl, Wsm);
    k_pair<<<dim3(8, L), 128>>>(pos, uid, Wd, Wiv, Wvmw, Wp1, Wp2, Wp3, Wb, outP);

    for (int b = 0; b < NBLK; b++) {
        k_gemm2<128,128,true ,false,false><<<L/8, 128>>>(pQbuf, Wq + (size_t)b*CA*CA, pQm);
        k_gemm2<128,128,true ,false,false><<<L/8, 128>>>(pQbuf, Wk + (size_t)b*CA*CA, pKm);
        k_gemm2<128,128,true ,false,false><<<L/8, 128>>>(pQbuf, Wv + (size_t)b*CA*CA, pVm);
        k_attn_split<<<dim3(L/128, NH, KSPLIT), 128>>>(b);
        k_attn_comb <<<L, 128>>>();
        k_gemm2<128,128,false,false,true ><<<L/8, 128>>>(pO, Wo + (size_t)b*CA*CA, pQbuf);
        k_gemm2<128,512,true ,true ,false><<<L/8, 128>>>(pQbuf, Wt1 + (size_t)b*CA*FFDIM, pFF);
        k_gemm2<512,128,false,false,true ><<<L/8, 128>>>(pFF, Wt2 + (size_t)b*FFDIM*CA, pQbuf);
    }

    k_copyQ<<<(L*CA)/256, 256>>>(outQ);
    k_gemm2<128,384,false,true,false><<<L/8, 128>>>(pQbuf, Wqtok, pFF);
    k_seg<<<TOKS, CT>>>(pFF, tok, outA);
}

// round 5
// speedup vs baseline: 1.2974x; 1.0663x over previous
#include <cuda_runtime.h>
#include <math.h>

#define L 2048
#define TOKS 512
#define CA 128
#define CP 16
#define CT 384
#define NH 4
#define HD 32
#define FFDIM 512
#define NBLK 3
#define F1D 388
#define KSPLIT 16

#define OFF_A 0
#define OFF_Q (TOKS*CT)
#define OFF_CL (OFF_Q + L*CA)
#define OFF_P (OFF_CL + L*CA)

typedef unsigned long long u64;

// ---------------- f32x2 helpers ----------------
__device__ __forceinline__ u64 pack2(float lo, float hi) {
    u64 r; asm("mov.b64 %0, {%1, %2};" : "=l"(r) : "f"(lo), "f"(hi)); return r;
}
__device__ __forceinline__ void unpack2(u64 v, float& lo, float& hi) {
    asm("mov.b64 {%0, %1}, %2;" : "=f"(lo), "=f"(hi) : "l"(v));
}
__device__ __forceinline__ u64 fma2(u64 a, u64 b, u64 c) {
    u64 d; asm("fma.rn.f32x2 %0, %1, %2, %3;" : "=l"(d) : "l"(a), "l"(b), "l"(c)); return d;
}
__device__ __forceinline__ u64 mul2(u64 a, u64 b) {
    u64 d; asm("mul.rn.f32x2 %0, %1, %2;" : "=l"(d) : "l"(a), "l"(b)); return d;
}
__device__ __forceinline__ u64 add2(u64 a, u64 b) {
    u64 d; asm("add.rn.f32x2 %0, %1, %2;" : "=l"(d) : "l"(a), "l"(b)); return d;
}
__device__ __forceinline__ u64 relu2(u64 v) {
    float lo, hi; unpack2(v, lo, hi);
    return pack2(fmaxf(lo, 0.f), fmaxf(hi, 0.f));
}

// ---------------- scratch ----------------
__device__ float g_Q  [L*CA];
__device__ float g_qm [L*CA];
__device__ float g_km [L*CA];
__device__ float g_vm [L*CA];
__device__ float g_o  [L*CA];
__device__ float g_ff [L*FFDIM];
__device__ float g_sl [L*CP];
__device__ float g_sm [L*CP];
__device__ float g_bias[(size_t)NBLK*NH*L*L];           // [b][h][l][m]
__device__ float g_pmax[KSPLIT*L*NH];
__device__ float g_psum[KSPLIT*L*NH];
__device__ float g_pacc[(size_t)KSPLIT*L*NH*HD];

// ---------------- C_L = concat(feat) @ W_in ; seeds residual Q ----------------
__global__ void k_cl(const float* __restrict__ pos, const float* __restrict__ charge,
                     const float* __restrict__ elem, const float* __restrict__ chars,
                     const float* __restrict__ Win, float* __restrict__ outCL)
{
    __shared__ float f[F1D];
    int l = blockIdx.x, t = threadIdx.x;
    if (t < 3)  f[t]   = pos[l*3 + t];
    if (t == 3) f[3]   = charge[l];
    f[4   + t] = elem [l*128 + t];
    f[132 + t] = chars[l*256 + t];
    f[260 + t] = chars[l*256 + 128 + t];
    __syncthreads();
    float acc = 0.f;
    #pragma unroll 4
    for (int k = 0; k < F1D; k++) acc += f[k] * Win[(size_t)k*CA + t];
    outCL[(size_t)l*CA + t] = acc;
    g_Q  [(size_t)l*CA + t] = acc;
}

// ---------------- sl = relu(C_L)@W_sl, sm = relu(C_L)@W_sm ----------------
__global__ void k_slsm(const float* __restrict__ CL, const float* __restrict__ Wsl,
                       const float* __restrict__ Wsm)
{
    __shared__ float r[128];
    int l = blockIdx.x, t = threadIdx.x;
    r[t] = fmaxf(CL[(size_t)l*128 + t], 0.f);
    __syncthreads();
    if (t < 16) {
        float a = 0.f;
        for (int k = 0; k < 128; k++) a += r[k] * Wsl[k*16 + t];
        g_sl[l*16 + t] = a;
    } else if (t < 32) {
        int c = t - 16;
        float a = 0.f;
        for (int k = 0; k < 128; k++) a += r[k] * Wsm[k*16 + c];
        g_sm[l*16 + c] = a;
    }
}

// ---------------- pair features + pair MLP + fused bias, 2 atoms/thread via f32x2 ----------------
__global__ void __launch_bounds__(128)
k_pair(const float* __restrict__ pos, const int* __restrict__ uid,
       const float* __restrict__ Wd,  const float* __restrict__ Wiv,
       const float* __restrict__ Wvm, const float* __restrict__ Wp1,
       const float* __restrict__ Wp2, const float* __restrict__ Wp3,
       const float* __restrict__ Wb,  float* __restrict__ outP)
{
    __shared__ u64 wd2[48], wiv2[16], wvm2[16], w1_2[256], w2_2[256], w3_2[256], wb2[192], sl2[16];
    __shared__ float pl[3];
    __shared__ int ul;
    int l = blockIdx.y;
    int t = threadIdx.x;
    int m0 = blockIdx.x*256 + t;
    int m1 = m0 + 128;

    if (t < 48) wd2[t] = pack2(Wd[t], Wd[t]);
    if (t < 16) {
        wiv2[t] = pack2(Wiv[t], Wiv[t]);
        wvm2[t] = pack2(Wvm[t], Wvm[t]);
        float s = g_sl[l*16 + t];
        sl2[t]  = pack2(s, s);
    }
    if (t < 3)  pl[t] = pos[l*3 + t];
    if (t == 0) ul = uid[l];
    w1_2[t] = pack2(Wp1[t], Wp1[t]); w1_2[t+128] = pack2(Wp1[t+128], Wp1[t+128]);
    w2_2[t] = pack2(Wp2[t], Wp2[t]); w2_2[t+128] = pack2(Wp2[t+128], Wp2[t+128]);
    w3_2[t] = pack2(Wp3[t], Wp3[t]); w3_2[t+128] = pack2(Wp3[t+128], Wp3[t+128]);
    wb2[t] = pack2(Wb[t], Wb[t]);
    if (t < 64) wb2[t+128] = pack2(Wb[t+128], Wb[t+128]);
    __syncthreads();

    float a0 = pl[0] - pos[m0*3+0], b0 = pl[1] - pos[m0*3+1], c0 = pl[2] - pos[m0*3+2];
    float a1 = pl[0] - pos[m1*3+0], b1 = pl[1] - pos[m1*3+1], c1 = pl[2] - pos[m1*3+2];
    float iv0 = 1.f / (1.f + sqrtf(a0*a0 + b0*b0 + c0*c0));
    float iv1 = 1.f / (1.f + sqrtf(a1*a1 + b1*b1 + c1*c1));
    float vf0 = (ul == uid[m0]) ? 1.f : 0.f;
    float vf1 = (ul == uid[m1]) ? 1.f : 0.f;
    u64 d0_2 = pack2(a0, a1), d1_2 = pack2(b0, b1), d2_2 = pack2(c0, c1);
    u64 iv2  = pack2(iv0, iv1), vf2 = pack2(vf0, vf1);

    // sm rows for both atoms
    u64 sm2[16];
    {
        const float4* r0 = (const float4*)(g_sm + m0*16);
        const float4* r1 = (const float4*)(g_sm + m1*16);
        #pragma unroll
        for (int i = 0; i < 4; i++) {
            float4 v0 = r0[i], v1 = r1[i];
            sm2[4*i+0] = pack2(v0.x, v1.x);
            sm2[4*i+1] = pack2(v0.y, v1.y);
            sm2[4*i+2] = pack2(v0.z, v1.z);
            sm2[4*i+3] = pack2(v0.w, v1.w);
        }
    }

    u64 p2[16];
    #pragma unroll
    for (int c = 0; c < 16; c++) {
        u64 tmp = wvm2[c];
        tmp = fma2(iv2,  wiv2[c],    tmp);
        tmp = fma2(d2_2, wd2[32+c],  tmp);
        tmp = fma2(d1_2, wd2[16+c],  tmp);
        tmp = fma2(d0_2, wd2[c],     tmp);
        p2[c] = fma2(vf2, tmp, add2(sl2[c], sm2[c]));
    }

    u64 pr2[16];
    #pragma unroll
    for (int c = 0; c < 16; c++) pr2[c] = relu2(p2[c]);

    u64 aa2[16];
    #pragma unroll
    for (int c = 0; c < 16; c++) {
        u64 s = 0ull;
        #pragma unroll
        for (int j = 0; j < 16; j++) s = fma2(pr2[j], w1_2[j*16 + c], s);
        aa2[c] = relu2(s);
    }
    #pragma unroll
    for (int c = 0; c < 16; c++) {
        u64 s = 0ull;
        #pragma unroll
        for (int j = 0; j < 16; j++) s = fma2(aa2[j], w2_2[j*16 + c], s);
        pr2[c] = relu2(s);
    }
    #pragma unroll
    for (int c = 0; c < 16; c++) {
        u64 s = 0ull;
        #pragma unroll
        for (int j = 0; j < 16; j++) s = fma2(pr2[j], w3_2[j*16 + c], s);
        p2[c] = add2(p2[c], s);
    }

    // store P (both rows)
    float plo[16], phi[16];
    #pragma unroll
    for (int c = 0; c < 16; c++) unpack2(p2[c], plo[c], phi[c]);
    {
        float4* dst0 = (float4*)(outP + ((size_t)l*L + m0)*16);
        float4* dst1 = (float4*)(outP + ((size_t)l*L + m1)*16);
        #pragma unroll
        for (int i = 0; i < 4; i++) {
            dst0[i] = make_float4(plo[4*i], plo[4*i+1], plo[4*i+2], plo[4*i+3]);
            dst1[i] = make_float4(phi[4*i], phi[4*i+1], phi[4*i+2], phi[4*i+3]);
        }
    }

    // fused bias for all 3 blocks x 4 heads
    #pragma unroll
    for (int b = 0; b < NBLK; b++) {
        #pragma unroll
        for (int h = 0; h < NH; h++) {
            u64 s = 0ull;
            #pragma unroll
            for (int c = 0; c < 16; c++) s = fma2(p2[c], wb2[b*64 + c*4 + h], s);
            float lo, hi; unpack2(s, lo, hi);
            float* base = g_bias + ((size_t)(b*NH + h)*L + l)*L;
            base[m0] = lo;
            base[m1] = hi;
        }
    }
}

// ---------------- high-occupancy row GEMM core: 256 threads, 8 rows/CTA ----------------
template<int K, int N, int NSUB, bool LNF, bool RELU, bool ADD>
__device__ __forceinline__ void gemm_core(const float* __restrict__ X,
                                          const float* __restrict__ W,
                                          float* __restrict__ OUT, int colOff)
{
    constexpr int R  = 8;
    constexpr int T  = 256;
    constexpr int NP = NSUB/2;       // col-pairs this launch-slice
    constexpr int G  = T/NP;         // row groups
    constexpr int RT = R/G;          // rows per thread
    __shared__ u64 xs2[R*K];

    int r0 = blockIdx.x * R;
    int t  = threadIdx.x;

    if (LNF) {
        // K == 128: one warp per row, float4 loads + shfl reduce
        int w = t >> 5, lane = t & 31;
        float4 v = ((const float4*)(X + (size_t)(r0 + w)*K))[lane];
        float s  = v.x + v.y + v.z + v.w;
        float ss = v.x*v.x + v.y*v.y + v.z*v.z + v.w*v.w;
        #pragma unroll
        for (int o = 16; o >= 1; o >>= 1) {
            s  += __shfl_xor_sync(0xffffffffu, s,  o);
            ss += __shfl_xor_sync(0xffffffffu, ss, o);
        }
        float mu   = s * (1.f/128.f);
        float rstd = rsqrtf(ss * (1.f/128.f) - mu*mu + 1e-5f);
        u64* xd = xs2 + w*K + lane*4;
        float n0 = (v.x - mu)*rstd, n1 = (v.y - mu)*rstd;
        float n2 = (v.z - mu)*rstd, n3 = (v.w - mu)*rstd;
        xd[0] = pack2(n0, n0); xd[1] = pack2(n1, n1);
        xd[2] = pack2(n2, n2); xd[3] = pack2(n3, n3);
    } else {
        const float* xb = X + (size_t)r0*K;
        for (int i = t; i < R*K; i += T) { float v = xb[i]; xs2[i] = pack2(v, v); }
    }
    __syncthreads();

    int cp = t % NP;
    int g  = t / NP;
    const u64* Wp = (const u64*)W + (colOff >> 1) + cp;
    u64 acc[RT];
    #pragma unroll
    for (int r = 0; r < RT; r++) acc[r] = 0ull;
    #pragma unroll 4
    for (int k = 0; k < K; k++) {
        u64 w2 = Wp[(size_t)k*(N/2)];
        #pragma unroll
        for (int r = 0; r < RT; r++)
            acc[r] = fma2(xs2[(g*RT + r)*K + k], w2, acc[r]);
    }
    #pragma unroll
    for (int r = 0; r < RT; r++) {
        float lo, hi; unpack2(acc[r], lo, hi);
        if (RELU) { lo = fmaxf(lo, 0.f); hi = fmaxf(hi, 0.f); }
        float* o = OUT + (size_t)(r0 + g*RT + r)*N + colOff + 2*cp;
        if (ADD) { o[0] += lo; o[1] += hi; }
        else     { o[0]  = lo; o[1]  = hi; }
    }
}

template<int K, int N, int NSUB, bool LNF, bool RELU, bool ADD>
__global__ void __launch_bounds__(256)
k_gemm8(const float* __restrict__ X, const float* __restrict__ W, float* __restrict__ OUT)
{
    gemm_core<K, N, NSUB, LNF, RELU, ADD>(X, W, OUT, blockIdx.y * NSUB);
}

// fused QKV: blockIdx.y selects matrix; LN fused
__global__ void __launch_bounds__(256)
k_qkv(const float* __restrict__ X, const float* __restrict__ Wq,
      const float* __restrict__ Wk, const float* __restrict__ Wv)
{
    const float* W = (blockIdx.y == 0) ? Wq : (blockIdx.y == 1) ? Wk : Wv;
    float* O = (blockIdx.y == 0) ? g_qm : (blockIdx.y == 1) ? g_km : g_vm;
    gemm_core<128, 128, 128, true, false, false>(X, W, O, 0);
}

// ---------------- attention: 128 queries x 1 head, key-split; f32x2 + LDS.128 ----------------
__global__ void __launch_bounds__(128) k_attn_split(int b)
{
    int h  = blockIdx.y;
    int s  = blockIdx.z;
    int q0 = blockIdx.x * 128;
    int t  = threadIdx.x;
    int q  = q0 + t;

    __shared__ alignas(16) float ks[32*32];
    __shared__ alignas(16) float vs[32*32];
    __shared__ float bs[128*33];

    u64 qr2[16];
    {
        const ulonglong2* q4 = (const ulonglong2*)(g_qm + (size_t)q*CA + h*HD);
        #pragma unroll
        for (int i = 0; i < 8; i++) {
            ulonglong2 v = q4[i];
            qr2[2*i]   = v.x;
            qr2[2*i+1] = v.y;
        }
    }

    float mmax = -1e30f, ssum = 0.f;
    u64 acc2[16];
    #pragma unroll
    for (int i = 0; i < 16; i++) acc2[i] = 0ull;
    const float scale = 0.1767766952966369f;

    const float* bsrc_base = g_bias + ((size_t)(b*NH + h)*L + q0)*L;
    int m_begin = s * (L/KSPLIT);
    int m_end   = m_begin + (L/KSPLIT);

    for (int m0 = m_begin; m0 < m_end; m0 += 32) {
        __syncthreads();
        for (int i = t; i < 256; i += 128) {
            int j = i >> 3, dq = i & 7;
            ((float4*)ks)[i] = ((const float4*)g_km)[(size_t)(m0+j)*32 + h*8 + dq];
            ((float4*)vs)[i] = ((const float4*)g_vm)[(size_t)(m0+j)*32 + h*8 + dq];
        }
        for (int i = t; i < 1024; i += 128) {
            int t2 = i >> 3, jv = i & 7;
            float4 v = *(const float4*)(bsrc_base + (size_t)t2*L + m0 + jv*4);
            float* d = bs + t2*33 + jv*4;
            d[0] = v.x; d[1] = v.y; d[2] = v.z; d[3] = v.w;
        }
        __syncthreads();

        #pragma unroll 2
        for (int j = 0; j < 32; j++) {
            const ulonglong2* k2 = (const ulonglong2*)(ks + j*32);
            u64 dpA = 0ull, dpB = 0ull;          // two chains for ILP
            #pragma unroll
            for (int i = 0; i < 4; i++) {
                ulonglong2 kk = k2[i];
                dpA = fma2(qr2[2*i],   kk.x, dpA);
                dpB = fma2(qr2[2*i+1], kk.y, dpB);
            }
            const ulonglong2* k2b = k2 + 4;
            #pragma unroll
            for (int i = 0; i < 4; i++) {
                ulonglong2 kk = k2b[i];
                dpA = fma2(qr2[8+2*i],   kk.x, dpA);
                dpB = fma2(qr2[8+2*i+1], kk.y, dpB);
            }
            u64 dp = add2(dpA, dpB);
            float dlo, dhi; unpack2(dp, dlo, dhi);
            float logit = (dlo + dhi) * scale + bs[t*33 + j];

            if (logit > mmax) {
                float f = __expf(mmax - logit);
                u64 f2 = pack2(f, f);
                ssum *= f;
                #pragma unroll
                for (int i = 0; i < 16; i++) acc2[i] = mul2(acc2[i], f2);
                mmax = logit;
            }
            float e = __expf(logit - mmax);
            ssum += e;
            u64 e2 = pack2(e, e);
            const ulonglong2* v2 = (const ulonglong2*)(vs + j*32);
            #pragma unroll
            for (int i = 0; i < 8; i++) {
                ulonglong2 vv = v2[i];
                acc2[2*i]   = fma2(e2, vv.x, acc2[2*i]);
                acc2[2*i+1] = fma2(e2, vv.y, acc2[2*i+1]);
            }
        }
    }

    int pidx = (s*L + q)*NH + h;
    g_pmax[pidx] = mmax;
    g_psum[pidx] = ssum;
    u64* pa = (u64*)(g_pacc + (size_t)pidx*HD);
    #pragma unroll
    for (int i = 0; i < 16; i++) pa[i] = acc2[i];
}

__global__ void k_attn_comb()
{
    int q = blockIdx.x;
    int t = threadIdx.x;            // 128 = 4 heads x 32 dims
    int h = t >> 5, d = t & 31;
    float pm[KSPLIT], gm = -1e30f;
    #pragma unroll
    for (int s = 0; s < KSPLIT; s++) {
        pm[s] = g_pmax[(s*L + q)*NH + h];
        gm = fmaxf(gm, pm[s]);
    }
    float denom = 0.f, o = 0.f;
    #pragma unroll
    for (int s = 0; s < KSPLIT; s++) {
        float f = __expf(pm[s] - gm);
        int pidx = (s*L + q)*NH + h;
        denom += g_psum[pidx] * f;
        o     += g_pacc[(size_t)pidx*HD + d] * f;
    }
    g_o[(size_t)q*CA + h*HD + d] = o / denom;
}

// ---------------- final Q copy ----------------
__global__ void k_copyQ(float* __restrict__ dst)
{
    int i = blockIdx.x*256 + threadIdx.x;
    dst[i] = g_Q[i];
}

// ---------------- segment mean ----------------
__global__ void k_seg(const float* __restrict__ pQ, const int* __restrict__ tok,
                      float* __restrict__ outA)
{
    __shared__ int slo, shi;
    int i = blockIdx.x;
    if (threadIdx.x == 0) {
        int lo = 0, hi = L;
        while (lo < hi) { int mid = (lo+hi) >> 1; if (tok[mid] < i) lo = mid+1; else hi = mid; }
        slo = lo;
        int lo2 = lo, hi2 = L;
        while (lo2 < hi2) { int mid = (lo2+hi2) >> 1; if (tok[mid] < i+1) lo2 = mid+1; else hi2 = mid; }
        shi = lo2;
    }
    __syncthreads();
    int lo = slo, hi = shi;
    float inv = (hi > lo) ? 1.f/(float)(hi - lo) : 0.f;
    int c = threadIdx.x;
    float a = 0.f;
    for (int at = lo; at < hi; at++) a += pQ[(size_t)at*CT + c];
    outA[(size_t)i*CT + c] = a * inv;
}

// ---------------- launch ----------------
extern "C" void kernel_launch(void* const* d_in, const int* in_sizes, int n_in,
                              void* d_out, int out_size)
{
    const float* pos    = (const float*)d_in[0];
    const float* charge = (const float*)d_in[1];
    const float* elem   = (const float*)d_in[2];
    const float* chars  = (const float*)d_in[3];
    const int*   uid    = (const int*)  d_in[4];
    const int*   tok    = (const int*)  d_in[5];
    const float* Win    = (const float*)d_in[6];
    const float* Wd     = (const float*)d_in[7];
    const float* Wiv    = (const float*)d_in[8];
    const float* Wvmw   = (const float*)d_in[9];
    const float* Wsl    = (const float*)d_in[10];
    const float* Wsm    = (const float*)d_in[11];
    const float* Wp1    = (const float*)d_in[12];
    const float* Wp2    = (const float*)d_in[13];
    const float* Wp3    = (const float*)d_in[14];
    const float* Wqtok  = (const float*)d_in[15];
    const float* Wq     = (const float*)d_in[16];
    const float* Wk     = (const float*)d_in[17];
    const float* Wv     = (const float*)d_in[18];
    const float* Wb     = (const float*)d_in[19];
    const float* Wo     = (const float*)d_in[20];
    const float* Wt1    = (const float*)d_in[21];
    const float* Wt2    = (const float*)d_in[22];

    float* out   = (float*)d_out;
    float* outA  = out + OFF_A;
    float* outQ  = out + OFF_Q;
    float* outCL = out + OFF_CL;
    float* outP  = out + OFF_P;

    float *pQbuf, *pO, *pFF;
    cudaGetSymbolAddress((void**)&pQbuf, g_Q);
    cudaGetSymbolAddress((void**)&pO,    g_o);
    cudaGetSymbolAddress((void**)&pFF,   g_ff);

    k_cl  <<<L, 128>>>(pos, charge, elem, chars, Win, outCL);
    k_slsm<<<L, 128>>>(outCL, Wsl, Wsm);
    k_pair<<<dim3(8, L), 128>>>(pos, uid, Wd, Wiv, Wvmw, Wp1, Wp2, Wp3, Wb, outP);

    for (int b = 0; b < NBLK; b++) {
        k_qkv<<<dim3(L/8, 3), 256>>>(pQbuf, Wq + (size_t)b*CA*CA,
                                     Wk + (size_t)b*CA*CA, Wv + (size_t)b*CA*CA);
        k_attn_split<<<dim3(L/128, NH, KSPLIT), 128>>>(b);
        k_attn_comb <<<L, 128>>>();
        k_gemm8<128,128,128,false,false,true ><<<dim3(L/8,1), 256>>>(pO, Wo + (size_t)b*CA*CA, pQbuf);
        k_gemm8<128,512,256,true ,true ,false><<<dim3(L/8,2), 256>>>(pQbuf, Wt1 + (size_t)b*CA*FFDIM, pFF);
        k_gemm8<512,128,128,false,false,true ><<<dim3(L/8,1), 256>>>(pFF, Wt2 + (size_t)b*FFDIM*CA, pQbuf);
    }

    k_copyQ<<<(L*CA)/256, 256>>>(outQ);
    k_gemm8<128,384,128,false,true,false><<<dim3(L/8,3), 256>>>(pQbuf, Wqtok, pFF);
    k_seg<<<TOKS, CT>>>(pFF, tok, outA);
}